// round 9
// baseline (speedup 1.0000x reference)
#include <cuda_runtime.h>
#include <cuda_bf16.h>
#include <cstdint>

#define NMAX 100000
#define EMAX 1600000
#define GMAX 128
#define HID  64
#define CAP  64      // ELL width; in-deg ~ Poisson(16), P(deg>=64) ~ 2e-18

// ---------------- scratch (no allocations allowed) ----------------
__device__ float g_dinv[NMAX];
__device__ int   g_deg[NMAX];
__device__ int   g_ell[(size_t)NMAX * CAP];
__device__ float g_bufZ[(size_t)NMAX * HID];    // y1 raw
__device__ float g_bufZ2[(size_t)NMAX * HID];   // z2
__device__ float g_pool[GMAX * HID];
__device__ float g_cnt[GMAX];

// ================= graph build (ELL, one edge pass) =================
__global__ void k_init(int n) {
    int i = blockIdx.x * blockDim.x + threadIdx.x;
    if (i < n) g_deg[i] = 0;
    if (i < GMAX * HID) g_pool[i] = 0.f;
    if (i < GMAX) g_cnt[i] = 0.f;
}

__global__ void k_ell_fill(const int* __restrict__ src,
                           const int* __restrict__ dst, int E) {
    int e = blockIdx.x * blockDim.x + threadIdx.x;
    if (e >= E) return;
    int d = dst[e];
    int p = atomicAdd(&g_deg[d], 1);
    g_ell[(size_t)d * CAP + p] = src[e];
}

__global__ void k_dinv(int n) {
    int i = blockIdx.x * blockDim.x + threadIdx.x;
    if (i < n) g_dinv[i] = rsqrtf((float)g_deg[i] + 1.0f);
}

// ================= fp32 tiled GEMM (layer 1, raw output) =================
template <int K>
__global__ void __launch_bounds__(256)
k_gemm1(const float* __restrict__ X,
        const float* __restrict__ Wg,
        float* __restrict__ Z, int n) {
    constexpr int BM = 128;
    constexpr int S  = K + 4;
    extern __shared__ float smf[];
    float* Xs = smf;
    float* Ws = smf + BM * S;

    const int tid  = threadIdx.x;
    const int base = blockIdx.x * BM;

    for (int i = tid; i < K * 16; i += 256)
        ((float4*)Ws)[i] = ((const float4*)Wg)[i];

    constexpr int F4 = K / 4;
    for (int f = tid; f < BM * F4; f += 256) {
        int m  = f / F4;
        int kc = f % F4;
        int node = base + m;
        float4 v = make_float4(0.f, 0.f, 0.f, 0.f);
        if (node < n) v = ((const float4*)(X + (size_t)node * K))[kc];
        *(float4*)(Xs + m * S + kc * 4) = v;
    }
    __syncthreads();

    const int row0 = (tid >> 3) * 4;
    const int col0 = (tid & 7) * 8;

    float acc[4][8];
#pragma unroll
    for (int i = 0; i < 4; i++)
#pragma unroll
        for (int j = 0; j < 8; j++) acc[i][j] = 0.f;

#pragma unroll 4
    for (int k = 0; k < K; k++) {
        float a0 = Xs[(row0 + 0) * S + k];
        float a1 = Xs[(row0 + 1) * S + k];
        float a2 = Xs[(row0 + 2) * S + k];
        float a3 = Xs[(row0 + 3) * S + k];
        float4 blo = *(float4*)(Ws + k * 64 + col0);
        float4 bhi = *(float4*)(Ws + k * 64 + col0 + 4);
        float b[8] = {blo.x, blo.y, blo.z, blo.w, bhi.x, bhi.y, bhi.z, bhi.w};
#pragma unroll
        for (int j = 0; j < 8; j++) {
            acc[0][j] = fmaf(a0, b[j], acc[0][j]);
            acc[1][j] = fmaf(a1, b[j], acc[1][j]);
            acc[2][j] = fmaf(a2, b[j], acc[2][j]);
            acc[3][j] = fmaf(a3, b[j], acc[3][j]);
        }
    }

#pragma unroll
    for (int i = 0; i < 4; i++) {
        int node = base + row0 + i;
        if (node < n) {
            float* zr = Z + (size_t)node * HID + col0;
            *(float4*)zr = make_float4(acc[i][0], acc[i][1], acc[i][2], acc[i][3]);
            *(float4*)(zr + 4) = make_float4(acc[i][4], acc[i][5], acc[i][6], acc[i][7]);
        }
    }
}

// ========== FUSED: aggregate-1 + input-transform + GEMM2 ==========
__global__ void __launch_bounds__(256)
k_agg_gemm2(const float* __restrict__ y1,
            const float* __restrict__ W2,     // [64][64]
            const float* __restrict__ b1,     // [64]
            float* __restrict__ Z2, int n) {
    constexpr int BM = 128;
    constexpr int K  = 64;
    constexpr int S  = K + 4;
    extern __shared__ float smf[];
    float* Xs = smf;                 // [128][68]
    float* Ws = smf + BM * S;        // [64][64]
    float* bs = Ws + K * 64;         // [64]

    const int tid  = threadIdx.x;
    const int base = blockIdx.x * BM;

    for (int i = tid; i < K * 16; i += 256)
        ((float4*)Ws)[i] = ((const float4*)W2)[i];
    if (tid < 64) bs[tid] = b1[tid];

    // ---- phase A: gather-aggregate into Xs ----
    const float4* z4 = (const float4*)y1;
#pragma unroll
    for (int p = 0; p < 8; p++) {
        int t  = tid + p * 256;          // 0..2047
        int m  = t >> 4;
        int jg = t & 15;
        int node = base + m;
        float4 acc = make_float4(0.f, 0.f, 0.f, 0.f);
        if (node < n) {
            float dn = __ldg(g_dinv + node);
            acc = __ldg(z4 + (size_t)node * 16 + jg);
            acc.x *= dn; acc.y *= dn; acc.z *= dn; acc.w *= dn;

            const int dg = __ldg(g_deg + node);
            const int* ep = g_ell + (size_t)node * CAP;
            int i = 0;
            float4 p0 = make_float4(0.f,0.f,0.f,0.f), p1 = p0;
            for (; i + 4 <= dg; i += 4) {
                int4 s4 = __ldg((const int4*)(ep + i));
                float4 v0 = __ldg(z4 + (size_t)s4.x * 16 + jg);
                float4 v1 = __ldg(z4 + (size_t)s4.y * 16 + jg);
                float4 v2 = __ldg(z4 + (size_t)s4.z * 16 + jg);
                float4 v3 = __ldg(z4 + (size_t)s4.w * 16 + jg);
                float d0 = __ldg(g_dinv + s4.x), d1 = __ldg(g_dinv + s4.y);
                float d2 = __ldg(g_dinv + s4.z), d3 = __ldg(g_dinv + s4.w);
                p0.x = fmaf(v0.x, d0, p0.x); p0.y = fmaf(v0.y, d0, p0.y);
                p0.z = fmaf(v0.z, d0, p0.z); p0.w = fmaf(v0.w, d0, p0.w);
                p0.x = fmaf(v1.x, d1, p0.x); p0.y = fmaf(v1.y, d1, p0.y);
                p0.z = fmaf(v1.z, d1, p0.z); p0.w = fmaf(v1.w, d1, p0.w);
                p1.x = fmaf(v2.x, d2, p1.x); p1.y = fmaf(v2.y, d2, p1.y);
                p1.z = fmaf(v2.z, d2, p1.z); p1.w = fmaf(v2.w, d2, p1.w);
                p1.x = fmaf(v3.x, d3, p1.x); p1.y = fmaf(v3.y, d3, p1.y);
                p1.z = fmaf(v3.z, d3, p1.z); p1.w = fmaf(v3.w, d3, p1.w);
            }
            for (; i < dg; i++) {
                int s0 = __ldg(ep + i);
                float4 v0 = __ldg(z4 + (size_t)s0 * 16 + jg);
                float d0 = __ldg(g_dinv + s0);
                p0.x = fmaf(v0.x, d0, p0.x); p0.y = fmaf(v0.y, d0, p0.y);
                p0.z = fmaf(v0.z, d0, p0.z); p0.w = fmaf(v0.w, d0, p0.w);
            }
            acc.x += p0.x + p1.x; acc.y += p0.y + p1.y;
            acc.z += p0.z + p1.z; acc.w += p0.w + p1.w;

            int k0 = jg * 4;
            acc.x = fmaxf(fmaf(acc.x, dn, bs[k0 + 0]), 0.f);
            acc.y = fmaxf(fmaf(acc.y, dn, bs[k0 + 1]), 0.f);
            acc.z = fmaxf(fmaf(acc.z, dn, bs[k0 + 2]), 0.f);
            acc.w = fmaxf(fmaf(acc.w, dn, bs[k0 + 3]), 0.f);
        }
        *(float4*)(Xs + m * S + jg * 4) = acc;
    }
    __syncthreads();

    // ---- phase B: tile GEMM, epilogue * dinv ----
    const int row0 = (tid >> 3) * 4;
    const int col0 = (tid & 7) * 8;

    float acc[4][8];
#pragma unroll
    for (int i = 0; i < 4; i++)
#pragma unroll
        for (int j = 0; j < 8; j++) acc[i][j] = 0.f;

#pragma unroll 4
    for (int k = 0; k < K; k++) {
        float a0 = Xs[(row0 + 0) * S + k];
        float a1 = Xs[(row0 + 1) * S + k];
        float a2 = Xs[(row0 + 2) * S + k];
        float a3 = Xs[(row0 + 3) * S + k];
        float4 blo = *(float4*)(Ws + k * 64 + col0);
        float4 bhi = *(float4*)(Ws + k * 64 + col0 + 4);
        float b[8] = {blo.x, blo.y, blo.z, blo.w, bhi.x, bhi.y, bhi.z, bhi.w};
#pragma unroll
        for (int j = 0; j < 8; j++) {
            acc[0][j] = fmaf(a0, b[j], acc[0][j]);
            acc[1][j] = fmaf(a1, b[j], acc[1][j]);
            acc[2][j] = fmaf(a2, b[j], acc[2][j]);
            acc[3][j] = fmaf(a3, b[j], acc[3][j]);
        }
    }

#pragma unroll
    for (int i = 0; i < 4; i++) {
        int node = base + row0 + i;
        if (node < n) {
            float di = g_dinv[node];
            float* zr = Z2 + (size_t)node * HID + col0;
            *(float4*)zr = make_float4(acc[i][0]*di, acc[i][1]*di,
                                       acc[i][2]*di, acc[i][3]*di);
            *(float4*)(zr + 4) = make_float4(acc[i][4]*di, acc[i][5]*di,
                                             acc[i][6]*di, acc[i][7]*di);
        }
    }
}

// ================= aggregate-2 fused with mean pool =================
__global__ void k_agg_pool(const float* __restrict__ z,
                           const int* __restrict__ batch, int n) {
    int t    = blockIdx.x * blockDim.x + threadIdx.x;
    int node = t >> 4;
    int jg   = t & 15;
    if (node >= n) return;

    const float4* z4 = (const float4*)z;
    float4 acc = __ldg(z4 + (size_t)node * 16 + jg);

    const int dg = __ldg(g_deg + node);
    const int* ep = g_ell + (size_t)node * CAP;

    int i = 0;
    float4 p0 = make_float4(0.f,0.f,0.f,0.f), p1 = p0;
    for (; i + 4 <= dg; i += 4) {
        int4 s4 = __ldg((const int4*)(ep + i));
        float4 v0 = __ldg(z4 + (size_t)s4.x * 16 + jg);
        float4 v1 = __ldg(z4 + (size_t)s4.y * 16 + jg);
        float4 v2 = __ldg(z4 + (size_t)s4.z * 16 + jg);
        float4 v3 = __ldg(z4 + (size_t)s4.w * 16 + jg);
        p0.x += v0.x + v1.x; p0.y += v0.y + v1.y;
        p0.z += v0.z + v1.z; p0.w += v0.w + v1.w;
        p1.x += v2.x + v3.x; p1.y += v2.y + v3.y;
        p1.z += v2.z + v3.z; p1.w += v2.w + v3.w;
    }
    for (; i < dg; i++) {
        int s0 = __ldg(ep + i);
        float4 v0 = __ldg(z4 + (size_t)s0 * 16 + jg);
        p0.x += v0.x; p0.y += v0.y; p0.z += v0.z; p0.w += v0.w;
    }
    acc.x += p0.x + p1.x; acc.y += p0.y + p1.y;
    acc.z += p0.z + p1.z; acc.w += p0.w + p1.w;

    float di = g_dinv[node];
    acc.x *= di; acc.y *= di; acc.z *= di; acc.w *= di;
    int g = __ldg(batch + node);
    atomicAdd((float4*)(g_pool + g * HID + jg * 4), acc);
    if (jg == 0) atomicAdd(&g_cnt[g], 1.0f);
}

__global__ void k_finalize(float* __restrict__ out,
                           const float* __restrict__ b2) {
    int t = blockIdx.x * blockDim.x + threadIdx.x;
    if (t >= GMAX * HID) return;
    int g = t >> 6, j = t & 63;
    out[t] = g_pool[t] / fmaxf(g_cnt[g], 1.0f) + b2[j];
}

// ================= launch =================
extern "C" void kernel_launch(void* const* d_in, const int* in_sizes, int n_in,
                              void* d_out, int out_size) {
    const float* x     = (const float*)d_in[0];
    const int*   eidx  = (const int*)d_in[1];
    const int*   batch = (const int*)d_in[2];
    const float* W1    = (const float*)d_in[3];
    const float* b1    = (const float*)d_in[4];
    const float* W2    = (const float*)d_in[5];
    const float* b2    = (const float*)d_in[6];
    float*       out   = (float*)d_out;

    const int n = in_sizes[0] / 128;
    const int E = in_sizes[1] / 2;
    const int* src = eidx;
    const int* dst = eidx + E;

    float *z, *z2;
    cudaGetSymbolAddress((void**)&z,  g_bufZ);
    cudaGetSymbolAddress((void**)&z2, g_bufZ2);

    const int B = 256;
    const int NBn = (n + 255) / 256;
    const int NBe = (E + 255) / 256;
    const int gemm_grid = (n + 127) / 128;
    const int agg_grid  = (n * 16 + B - 1) / B;

    const int smem1 = (128 * (128 + 4) + 128 * 64) * 4;        // 100352 B
    const int smemF = (128 * (64 + 4) + 64 * 64 + 64) * 4;     // 51456 B
    cudaFuncSetAttribute(k_gemm1<128>,
                         cudaFuncAttributeMaxDynamicSharedMemorySize, smem1);
    cudaFuncSetAttribute(k_agg_gemm2,
                         cudaFuncAttributeMaxDynamicSharedMemorySize, smemF);

    cudaStream_t s2;
    cudaStreamCreateWithFlags(&s2, cudaStreamNonBlocking);
    cudaEvent_t evFork, evJoin;
    cudaEventCreateWithFlags(&evFork, cudaEventDisableTiming);
    cudaEventCreateWithFlags(&evJoin, cudaEventDisableTiming);

    cudaEventRecord(evFork, 0);
    cudaStreamWaitEvent(s2, evFork, 0);

    // side stream: ELL build (1 edge pass) + dinv + pool zeroing
    k_init<<<NBn, B, 0, s2>>>(n);
    k_ell_fill<<<NBe, B, 0, s2>>>(src, dst, E);
    k_dinv<<<NBn, B, 0, s2>>>(n);

    // main stream: layer-1 GEMM (raw y1 = x@W1, no graph dependence)
    k_gemm1<128><<<gemm_grid, 256, smem1>>>(x, W1, z, n);

    cudaEventRecord(evJoin, s2);
    cudaStreamWaitEvent(0, evJoin, 0);

    // fused aggregate-1 + transform + GEMM2 -> z2
    k_agg_gemm2<<<gemm_grid, 256, smemF>>>(z, W2, b1, z2, n);

    // aggregate-2 fused with mean pool
    k_agg_pool<<<agg_grid, B>>>(z2, batch, n);
    k_finalize<<<(GMAX * HID + B - 1) / B, B>>>(out, b2);
}

// round 10
// speedup vs baseline: 1.0704x; 1.0704x over previous
#include <cuda_runtime.h>
#include <cuda_bf16.h>
#include <cstdint>

#define NMAX 100000
#define EMAX 1600000
#define GMAX 128
#define HID  64
#define CAP  64      // ELL width; in-deg ~ Poisson(16), P(deg>=64) ~ 1e-13 overall

// ---------------- scratch (no allocations allowed) ----------------
__device__ float g_dinv[NMAX];
__device__ int   g_deg[NMAX];
__device__ int   g_ell[(size_t)NMAX * CAP];
__device__ float g_bufZ[(size_t)NMAX * HID];    // y1 raw
__device__ float g_bufZ2[(size_t)NMAX * HID];   // z2
__device__ float g_pool[GMAX * HID];
__device__ float g_cnt[GMAX];

// ================= graph build (ELL, one edge pass) =================
__global__ void k_init(int n) {
    int i = blockIdx.x * blockDim.x + threadIdx.x;
    if (i < n) g_deg[i] = 0;
    if (i < GMAX * HID) g_pool[i] = 0.f;
    if (i < GMAX) g_cnt[i] = 0.f;
}

__global__ void k_ell_fill(const int* __restrict__ src,
                           const int* __restrict__ dst, int E) {
    int e = blockIdx.x * blockDim.x + threadIdx.x;
    if (e >= E) return;
    int d = dst[e];
    int p = atomicAdd(&g_deg[d], 1);
    g_ell[(size_t)d * CAP + p] = src[e];
}

__global__ void k_dinv(int n) {
    int i = blockIdx.x * blockDim.x + threadIdx.x;
    if (i < n) g_dinv[i] = rsqrtf((float)g_deg[i] + 1.0f);
}

// ================= split-K tiled GEMM (layer 1, raw output) ==========
// BM=128 nodes x 64 cols, K=128 processed in 2 chunks of 64 so the smem
// footprint is 67.6KB -> 3 CTAs/SM (24 warps) instead of 2 (16 warps).
__global__ void __launch_bounds__(256)
k_gemm1(const float* __restrict__ X,
        const float* __restrict__ Wg,
        float* __restrict__ Z, int n) {
    constexpr int K  = 128;
    constexpr int KC = 64;           // K chunk
    constexpr int S  = KC + 4;       // X-tile row stride
    extern __shared__ float smf[];
    float* Xs = smf;                 // [128][68]
    float* Ws = smf + 128 * S;       // [128][64]

    const int tid  = threadIdx.x;
    const int base = blockIdx.x * 128;

    // load full W once (coalesced float4)
    for (int i = tid; i < K * 16; i += 256)
        ((float4*)Ws)[i] = ((const float4*)Wg)[i];

    const int row0 = (tid >> 3) * 4;
    const int col0 = (tid & 7) * 8;

    float acc[4][8];
#pragma unroll
    for (int i = 0; i < 4; i++)
#pragma unroll
        for (int j = 0; j < 8; j++) acc[i][j] = 0.f;

#pragma unroll
    for (int c = 0; c < K / KC; c++) {
        __syncthreads();            // protect Xs overwrite (and W on 1st iter)
        // load X chunk: 128 rows x 16 float4
        for (int f = tid; f < 128 * (KC / 4); f += 256) {
            int m  = f >> 4;
            int kc = f & 15;
            int node = base + m;
            float4 v = make_float4(0.f, 0.f, 0.f, 0.f);
            if (node < n)
                v = ((const float4*)(X + (size_t)node * K + c * KC))[kc];
            *(float4*)(Xs + m * S + kc * 4) = v;
        }
        __syncthreads();

#pragma unroll 4
        for (int k = 0; k < KC; k++) {
            float a0 = Xs[(row0 + 0) * S + k];
            float a1 = Xs[(row0 + 1) * S + k];
            float a2 = Xs[(row0 + 2) * S + k];
            float a3 = Xs[(row0 + 3) * S + k];
            const float* wrow = Ws + (c * KC + k) * 64 + col0;
            float4 blo = *(const float4*)wrow;
            float4 bhi = *(const float4*)(wrow + 4);
            float b[8] = {blo.x, blo.y, blo.z, blo.w, bhi.x, bhi.y, bhi.z, bhi.w};
#pragma unroll
            for (int j = 0; j < 8; j++) {
                acc[0][j] = fmaf(a0, b[j], acc[0][j]);
                acc[1][j] = fmaf(a1, b[j], acc[1][j]);
                acc[2][j] = fmaf(a2, b[j], acc[2][j]);
                acc[3][j] = fmaf(a3, b[j], acc[3][j]);
            }
        }
    }

#pragma unroll
    for (int i = 0; i < 4; i++) {
        int node = base + row0 + i;
        if (node < n) {
            float* zr = Z + (size_t)node * HID + col0;
            *(float4*)zr = make_float4(acc[i][0], acc[i][1], acc[i][2], acc[i][3]);
            *(float4*)(zr + 4) = make_float4(acc[i][4], acc[i][5], acc[i][6], acc[i][7]);
        }
    }
}

// ========== FUSED: aggregate-1 + input-transform + GEMM2 ==========
__global__ void __launch_bounds__(256)
k_agg_gemm2(const float* __restrict__ y1,
            const float* __restrict__ W2,     // [64][64]
            const float* __restrict__ b1,     // [64]
            float* __restrict__ Z2, int n) {
    constexpr int BM = 128;
    constexpr int K  = 64;
    constexpr int S  = K + 4;
    extern __shared__ float smf[];
    float* Xs = smf;                 // [128][68]
    float* Ws = smf + BM * S;        // [64][64]
    float* bs = Ws + K * 64;         // [64]

    const int tid  = threadIdx.x;
    const int base = blockIdx.x * BM;

    for (int i = tid; i < K * 16; i += 256)
        ((float4*)Ws)[i] = ((const float4*)W2)[i];
    if (tid < 64) bs[tid] = b1[tid];

    // ---- phase A: gather-aggregate into Xs ----
    const float4* z4 = (const float4*)y1;
#pragma unroll
    for (int p = 0; p < 8; p++) {
        int t  = tid + p * 256;          // 0..2047
        int m  = t >> 4;
        int jg = t & 15;
        int node = base + m;
        float4 acc = make_float4(0.f, 0.f, 0.f, 0.f);
        if (node < n) {
            float dn = __ldg(g_dinv + node);
            acc = __ldg(z4 + (size_t)node * 16 + jg);
            acc.x *= dn; acc.y *= dn; acc.z *= dn; acc.w *= dn;

            const int dg = __ldg(g_deg + node);
            const int* ep = g_ell + (size_t)node * CAP;
            int i = 0;
            float4 p0 = make_float4(0.f,0.f,0.f,0.f), p1 = p0;
            for (; i + 4 <= dg; i += 4) {
                int4 s4 = __ldg((const int4*)(ep + i));
                float4 v0 = __ldg(z4 + (size_t)s4.x * 16 + jg);
                float4 v1 = __ldg(z4 + (size_t)s4.y * 16 + jg);
                float4 v2 = __ldg(z4 + (size_t)s4.z * 16 + jg);
                float4 v3 = __ldg(z4 + (size_t)s4.w * 16 + jg);
                float d0 = __ldg(g_dinv + s4.x), d1 = __ldg(g_dinv + s4.y);
                float d2 = __ldg(g_dinv + s4.z), d3 = __ldg(g_dinv + s4.w);
                p0.x = fmaf(v0.x, d0, p0.x); p0.y = fmaf(v0.y, d0, p0.y);
                p0.z = fmaf(v0.z, d0, p0.z); p0.w = fmaf(v0.w, d0, p0.w);
                p0.x = fmaf(v1.x, d1, p0.x); p0.y = fmaf(v1.y, d1, p0.y);
                p0.z = fmaf(v1.z, d1, p0.z); p0.w = fmaf(v1.w, d1, p0.w);
                p1.x = fmaf(v2.x, d2, p1.x); p1.y = fmaf(v2.y, d2, p1.y);
                p1.z = fmaf(v2.z, d2, p1.z); p1.w = fmaf(v2.w, d2, p1.w);
                p1.x = fmaf(v3.x, d3, p1.x); p1.y = fmaf(v3.y, d3, p1.y);
                p1.z = fmaf(v3.z, d3, p1.z); p1.w = fmaf(v3.w, d3, p1.w);
            }
            for (; i < dg; i++) {
                int s0 = __ldg(ep + i);
                float4 v0 = __ldg(z4 + (size_t)s0 * 16 + jg);
                float d0 = __ldg(g_dinv + s0);
                p0.x = fmaf(v0.x, d0, p0.x); p0.y = fmaf(v0.y, d0, p0.y);
                p0.z = fmaf(v0.z, d0, p0.z); p0.w = fmaf(v0.w, d0, p0.w);
            }
            acc.x += p0.x + p1.x; acc.y += p0.y + p1.y;
            acc.z += p0.z + p1.z; acc.w += p0.w + p1.w;

            int k0 = jg * 4;
            acc.x = fmaxf(fmaf(acc.x, dn, bs[k0 + 0]), 0.f);
            acc.y = fmaxf(fmaf(acc.y, dn, bs[k0 + 1]), 0.f);
            acc.z = fmaxf(fmaf(acc.z, dn, bs[k0 + 2]), 0.f);
            acc.w = fmaxf(fmaf(acc.w, dn, bs[k0 + 3]), 0.f);
        }
        *(float4*)(Xs + m * S + jg * 4) = acc;
    }
    __syncthreads();

    // ---- phase B: tile GEMM, epilogue * dinv ----
    const int row0 = (tid >> 3) * 4;
    const int col0 = (tid & 7) * 8;

    float acc[4][8];
#pragma unroll
    for (int i = 0; i < 4; i++)
#pragma unroll
        for (int j = 0; j < 8; j++) acc[i][j] = 0.f;

#pragma unroll 4
    for (int k = 0; k < K; k++) {
        float a0 = Xs[(row0 + 0) * S + k];
        float a1 = Xs[(row0 + 1) * S + k];
        float a2 = Xs[(row0 + 2) * S + k];
        float a3 = Xs[(row0 + 3) * S + k];
        float4 blo = *(float4*)(Ws + k * 64 + col0);
        float4 bhi = *(float4*)(Ws + k * 64 + col0 + 4);
        float b[8] = {blo.x, blo.y, blo.z, blo.w, bhi.x, bhi.y, bhi.z, bhi.w};
#pragma unroll
        for (int j = 0; j < 8; j++) {
            acc[0][j] = fmaf(a0, b[j], acc[0][j]);
            acc[1][j] = fmaf(a1, b[j], acc[1][j]);
            acc[2][j] = fmaf(a2, b[j], acc[2][j]);
            acc[3][j] = fmaf(a3, b[j], acc[3][j]);
        }
    }

#pragma unroll
    for (int i = 0; i < 4; i++) {
        int node = base + row0 + i;
        if (node < n) {
            float di = g_dinv[node];
            float* zr = Z2 + (size_t)node * HID + col0;
            *(float4*)zr = make_float4(acc[i][0]*di, acc[i][1]*di,
                                       acc[i][2]*di, acc[i][3]*di);
            *(float4*)(zr + 4) = make_float4(acc[i][4]*di, acc[i][5]*di,
                                             acc[i][6]*di, acc[i][7]*di);
        }
    }
}

// ================= aggregate-2 fused with mean pool =================
__global__ void k_agg_pool(const float* __restrict__ z,
                           const int* __restrict__ batch, int n) {
    int t    = blockIdx.x * blockDim.x + threadIdx.x;
    int node = t >> 4;
    int jg   = t & 15;
    if (node >= n) return;

    const float4* z4 = (const float4*)z;
    float4 acc = __ldg(z4 + (size_t)node * 16 + jg);

    const int dg = __ldg(g_deg + node);
    const int* ep = g_ell + (size_t)node * CAP;

    int i = 0;
    float4 p0 = make_float4(0.f,0.f,0.f,0.f), p1 = p0;
    for (; i + 4 <= dg; i += 4) {
        int4 s4 = __ldg((const int4*)(ep + i));
        float4 v0 = __ldg(z4 + (size_t)s4.x * 16 + jg);
        float4 v1 = __ldg(z4 + (size_t)s4.y * 16 + jg);
        float4 v2 = __ldg(z4 + (size_t)s4.z * 16 + jg);
        float4 v3 = __ldg(z4 + (size_t)s4.w * 16 + jg);
        p0.x += v0.x + v1.x; p0.y += v0.y + v1.y;
        p0.z += v0.z + v1.z; p0.w += v0.w + v1.w;
        p1.x += v2.x + v3.x; p1.y += v2.y + v3.y;
        p1.z += v2.z + v3.z; p1.w += v2.w + v3.w;
    }
    for (; i < dg; i++) {
        int s0 = __ldg(ep + i);
        float4 v0 = __ldg(z4 + (size_t)s0 * 16 + jg);
        p0.x += v0.x; p0.y += v0.y; p0.z += v0.z; p0.w += v0.w;
    }
    acc.x += p0.x + p1.x; acc.y += p0.y + p1.y;
    acc.z += p0.z + p1.z; acc.w += p0.w + p1.w;

    float di = g_dinv[node];
    acc.x *= di; acc.y *= di; acc.z *= di; acc.w *= di;
    int g = __ldg(batch + node);
    atomicAdd((float4*)(g_pool + g * HID + jg * 4), acc);
    if (jg == 0) atomicAdd(&g_cnt[g], 1.0f);
}

__global__ void k_finalize(float* __restrict__ out,
                           const float* __restrict__ b2) {
    int t = blockIdx.x * blockDim.x + threadIdx.x;
    if (t >= GMAX * HID) return;
    int g = t >> 6, j = t & 63;
    out[t] = g_pool[t] / fmaxf(g_cnt[g], 1.0f) + b2[j];
}

// ================= launch (single stream, serial) =================
extern "C" void kernel_launch(void* const* d_in, const int* in_sizes, int n_in,
                              void* d_out, int out_size) {
    const float* x     = (const float*)d_in[0];
    const int*   eidx  = (const int*)d_in[1];
    const int*   batch = (const int*)d_in[2];
    const float* W1    = (const float*)d_in[3];
    const float* b1    = (const float*)d_in[4];
    const float* W2    = (const float*)d_in[5];
    const float* b2    = (const float*)d_in[6];
    float*       out   = (float*)d_out;

    const int n = in_sizes[0] / 128;
    const int E = in_sizes[1] / 2;
    const int* src = eidx;
    const int* dst = eidx + E;

    float *z, *z2;
    cudaGetSymbolAddress((void**)&z,  g_bufZ);
    cudaGetSymbolAddress((void**)&z2, g_bufZ2);

    const int B = 256;
    const int NBn = (n + 255) / 256;
    const int NBe = (E + 255) / 256;
    const int gemm_grid = (n + 127) / 128;
    const int agg_grid  = (n * 16 + B - 1) / B;

    const int smem1 = (128 * (64 + 4) + 128 * 64) * 4;         // 67584 B
    const int smemF = (128 * (64 + 4) + 64 * 64 + 64) * 4;     // 51456 B
    cudaFuncSetAttribute(k_gemm1,
                         cudaFuncAttributeMaxDynamicSharedMemorySize, smem1);
    cudaFuncSetAttribute(k_agg_gemm2,
                         cudaFuncAttributeMaxDynamicSharedMemorySize, smemF);

    // ELL build (1 edge pass) + dinv + pool zeroing
    k_init<<<NBn, B>>>(n);
    k_ell_fill<<<NBe, B>>>(src, dst, E);
    k_dinv<<<NBn, B>>>(n);

    // layer-1 GEMM (raw y1 = x@W1), split-K for occupancy
    k_gemm1<<<gemm_grid, 256, smem1>>>(x, W1, z, n);

    // fused aggregate-1 + transform + GEMM2 -> z2
    k_agg_gemm2<<<gemm_grid, 256, smemF>>>(z, W2, b1, z2, n);

    // aggregate-2 fused with mean pool
    k_agg_pool<<<agg_grid, B>>>(z2, batch, n);
    k_finalize<<<(GMAX * HID + B - 1) / B, B>>>(out, b2);
}

// round 11
// speedup vs baseline: 1.1595x; 1.0832x over previous
#include <cuda_runtime.h>
#include <cuda_bf16.h>
#include <cstdint>

#define NMAX 100000
#define EMAX 1600000
#define GMAX 128
#define HID  64
#define CAP  64      // ELL width; in-deg ~ Poisson(16), P(overflow) ~ 1e-13

// ---------------- scratch (no allocations allowed) ----------------
__device__ float g_dinv[NMAX];
__device__ int   g_deg[NMAX];
__device__ int   g_ell[(size_t)NMAX * CAP];
__device__ float g_bufZ[(size_t)NMAX * HID];    // z1 = (x@W1)*dinv
__device__ float g_bufZ2[(size_t)NMAX * HID];   // z2
__device__ float g_pool[GMAX * HID];
__device__ float g_cnt[GMAX];

__device__ __forceinline__ void add4(float4& a, const float4 b) {
    a.x += b.x; a.y += b.y; a.z += b.z; a.w += b.w;
}

// ================= graph build (ELL, one edge pass) =================
__global__ void k_init(int n) {
    int i = blockIdx.x * blockDim.x + threadIdx.x;
    if (i < n) g_deg[i] = 0;
    if (i < GMAX * HID) g_pool[i] = 0.f;
    if (i < GMAX) g_cnt[i] = 0.f;
}

__global__ void k_ell_fill(const int* __restrict__ src,
                           const int* __restrict__ dst, int E) {
    int e = blockIdx.x * blockDim.x + threadIdx.x;
    if (e >= E) return;
    int d = dst[e];
    int p = atomicAdd(&g_deg[d], 1);
    g_ell[(size_t)d * CAP + p] = src[e];
}

__global__ void k_dinv(int n) {
    int i = blockIdx.x * blockDim.x + threadIdx.x;
    if (i < n) g_dinv[i] = rsqrtf((float)g_deg[i] + 1.0f);
}

// ================= split-K tiled GEMM (layer 1) =================
// z1[node,:] = (x[node,:] @ W1) * dinv[node]   (prescaled messages)
__global__ void __launch_bounds__(256)
k_gemm1(const float* __restrict__ X,
        const float* __restrict__ Wg,
        float* __restrict__ Z, int n) {
    constexpr int K  = 128;
    constexpr int KC = 64;
    constexpr int S  = KC + 4;
    extern __shared__ float smf[];
    float* Xs = smf;                 // [128][68]
    float* Ws = smf + 128 * S;       // [128][64]

    const int tid  = threadIdx.x;
    const int base = blockIdx.x * 128;

    for (int i = tid; i < K * 16; i += 256)
        ((float4*)Ws)[i] = ((const float4*)Wg)[i];

    const int row0 = (tid >> 3) * 4;
    const int col0 = (tid & 7) * 8;

    float acc[4][8];
#pragma unroll
    for (int i = 0; i < 4; i++)
#pragma unroll
        for (int j = 0; j < 8; j++) acc[i][j] = 0.f;

#pragma unroll
    for (int c = 0; c < K / KC; c++) {
        __syncthreads();
        for (int f = tid; f < 128 * (KC / 4); f += 256) {
            int m  = f >> 4;
            int kc = f & 15;
            int node = base + m;
            float4 v = make_float4(0.f, 0.f, 0.f, 0.f);
            if (node < n)
                v = ((const float4*)(X + (size_t)node * K + c * KC))[kc];
            *(float4*)(Xs + m * S + kc * 4) = v;
        }
        __syncthreads();

#pragma unroll 4
        for (int k = 0; k < KC; k++) {
            float a0 = Xs[(row0 + 0) * S + k];
            float a1 = Xs[(row0 + 1) * S + k];
            float a2 = Xs[(row0 + 2) * S + k];
            float a3 = Xs[(row0 + 3) * S + k];
            const float* wrow = Ws + (c * KC + k) * 64 + col0;
            float4 blo = *(const float4*)wrow;
            float4 bhi = *(const float4*)(wrow + 4);
            float b[8] = {blo.x, blo.y, blo.z, blo.w, bhi.x, bhi.y, bhi.z, bhi.w};
#pragma unroll
            for (int j = 0; j < 8; j++) {
                acc[0][j] = fmaf(a0, b[j], acc[0][j]);
                acc[1][j] = fmaf(a1, b[j], acc[1][j]);
                acc[2][j] = fmaf(a2, b[j], acc[2][j]);
                acc[3][j] = fmaf(a3, b[j], acc[3][j]);
            }
        }
    }

#pragma unroll
    for (int i = 0; i < 4; i++) {
        int node = base + row0 + i;
        if (node < n) {
            float di = g_dinv[node];          // prescale messages
            float* zr = Z + (size_t)node * HID + col0;
            *(float4*)zr = make_float4(acc[i][0]*di, acc[i][1]*di,
                                       acc[i][2]*di, acc[i][3]*di);
            *(float4*)(zr + 4) = make_float4(acc[i][4]*di, acc[i][5]*di,
                                             acc[i][6]*di, acc[i][7]*di);
        }
    }
}

// ========== FUSED: aggregate-1 + input-transform + GEMM2 ==========
// Phase A (8 lanes/node, 32B each): S = z1[d] + Σ z1[s];
//   x2 = relu(dinv[d]*S + b1)  -> GEMM X-tile in smem.
// Phase B: z2 = (x2 @ W2) * dinv[d]
__global__ void __launch_bounds__(256)
k_agg_gemm2(const float* __restrict__ z1,
            const float* __restrict__ W2,
            const float* __restrict__ b1,
            float* __restrict__ Z2, int n) {
    constexpr int BM = 128;
    constexpr int K  = 64;
    constexpr int S  = K + 4;
    extern __shared__ float smf[];
    float* Xs = smf;                 // [128][68]
    float* Ws = smf + BM * S;        // [64][64]
    float* bs = Ws + K * 64;         // [64]

    const int tid  = threadIdx.x;
    const int base = blockIdx.x * BM;

    for (int i = tid; i < K * 16; i += 256)
        ((float4*)Ws)[i] = ((const float4*)W2)[i];
    if (tid < 64) bs[tid] = b1[tid];

    const float4* z4 = (const float4*)z1;
#pragma unroll
    for (int p = 0; p < 4; p++) {               // 128 nodes * 8 lanes = 1024
        int t  = tid + p * 256;
        int m  = t >> 3;
        int jg = t & 7;                          // lane owns cols jg*8..jg*8+7
        int node = base + m;
        float4 acc0 = make_float4(0.f,0.f,0.f,0.f), acc1 = acc0;
        if (node < n) {
            const float4* zr = z4 + (size_t)node * 16 + jg * 2;
            acc0 = __ldg(zr);
            acc1 = __ldg(zr + 1);

            const int dg = __ldg(g_deg + node);
            const int* ep = g_ell + (size_t)node * CAP;
            int i = 0;
            for (; i + 4 <= dg; i += 4) {
                int4 s4 = __ldg((const int4*)(ep + i));
                const float4* r0 = z4 + (size_t)s4.x * 16 + jg * 2;
                const float4* r1 = z4 + (size_t)s4.y * 16 + jg * 2;
                const float4* r2 = z4 + (size_t)s4.z * 16 + jg * 2;
                const float4* r3 = z4 + (size_t)s4.w * 16 + jg * 2;
                float4 v0a = __ldg(r0), v0b = __ldg(r0 + 1);
                float4 v1a = __ldg(r1), v1b = __ldg(r1 + 1);
                float4 v2a = __ldg(r2), v2b = __ldg(r2 + 1);
                float4 v3a = __ldg(r3), v3b = __ldg(r3 + 1);
                add4(acc0, v0a); add4(acc1, v0b);
                add4(acc0, v1a); add4(acc1, v1b);
                add4(acc0, v2a); add4(acc1, v2b);
                add4(acc0, v3a); add4(acc1, v3b);
            }
            for (; i < dg; i++) {
                int s0 = __ldg(ep + i);
                const float4* r0 = z4 + (size_t)s0 * 16 + jg * 2;
                add4(acc0, __ldg(r0));
                add4(acc1, __ldg(r0 + 1));
            }

            float dn = __ldg(g_dinv + node);
            int k0 = jg * 8;
            acc0.x = fmaxf(fmaf(acc0.x, dn, bs[k0 + 0]), 0.f);
            acc0.y = fmaxf(fmaf(acc0.y, dn, bs[k0 + 1]), 0.f);
            acc0.z = fmaxf(fmaf(acc0.z, dn, bs[k0 + 2]), 0.f);
            acc0.w = fmaxf(fmaf(acc0.w, dn, bs[k0 + 3]), 0.f);
            acc1.x = fmaxf(fmaf(acc1.x, dn, bs[k0 + 4]), 0.f);
            acc1.y = fmaxf(fmaf(acc1.y, dn, bs[k0 + 5]), 0.f);
            acc1.z = fmaxf(fmaf(acc1.z, dn, bs[k0 + 6]), 0.f);
            acc1.w = fmaxf(fmaf(acc1.w, dn, bs[k0 + 7]), 0.f);
        }
        *(float4*)(Xs + m * S + jg * 8)     = acc0;
        *(float4*)(Xs + m * S + jg * 8 + 4) = acc1;
    }
    __syncthreads();

    // ---- phase B: tile GEMM, epilogue * dinv ----
    const int row0 = (tid >> 3) * 4;
    const int col0 = (tid & 7) * 8;

    float acc[4][8];
#pragma unroll
    for (int i = 0; i < 4; i++)
#pragma unroll
        for (int j = 0; j < 8; j++) acc[i][j] = 0.f;

#pragma unroll 4
    for (int k = 0; k < K; k++) {
        float a0 = Xs[(row0 + 0) * S + k];
        float a1 = Xs[(row0 + 1) * S + k];
        float a2 = Xs[(row0 + 2) * S + k];
        float a3 = Xs[(row0 + 3) * S + k];
        float4 blo = *(float4*)(Ws + k * 64 + col0);
        float4 bhi = *(float4*)(Ws + k * 64 + col0 + 4);
        float b[8] = {blo.x, blo.y, blo.z, blo.w, bhi.x, bhi.y, bhi.z, bhi.w};
#pragma unroll
        for (int j = 0; j < 8; j++) {
            acc[0][j] = fmaf(a0, b[j], acc[0][j]);
            acc[1][j] = fmaf(a1, b[j], acc[1][j]);
            acc[2][j] = fmaf(a2, b[j], acc[2][j]);
            acc[3][j] = fmaf(a3, b[j], acc[3][j]);
        }
    }

#pragma unroll
    for (int i = 0; i < 4; i++) {
        int node = base + row0 + i;
        if (node < n) {
            float di = g_dinv[node];
            float* zr = Z2 + (size_t)node * HID + col0;
            *(float4*)zr = make_float4(acc[i][0]*di, acc[i][1]*di,
                                       acc[i][2]*di, acc[i][3]*di);
            *(float4*)(zr + 4) = make_float4(acc[i][4]*di, acc[i][5]*di,
                                             acc[i][6]*di, acc[i][7]*di);
        }
    }
}

// ============ aggregate-2 (8 lanes/node) fused with mean pool ============
__global__ void k_agg_pool(const float* __restrict__ z,
                           const int* __restrict__ batch, int n) {
    int t    = blockIdx.x * blockDim.x + threadIdx.x;
    int node = t >> 3;
    int jg   = t & 7;
    if (node >= n) return;

    const float4* z4 = (const float4*)z;
    const float4* zr = z4 + (size_t)node * 16 + jg * 2;
    float4 acc0 = __ldg(zr);
    float4 acc1 = __ldg(zr + 1);

    const int dg = __ldg(g_deg + node);
    const int* ep = g_ell + (size_t)node * CAP;

    int i = 0;
    for (; i + 4 <= dg; i += 4) {
        int4 s4 = __ldg((const int4*)(ep + i));
        const float4* r0 = z4 + (size_t)s4.x * 16 + jg * 2;
        const float4* r1 = z4 + (size_t)s4.y * 16 + jg * 2;
        const float4* r2 = z4 + (size_t)s4.z * 16 + jg * 2;
        const float4* r3 = z4 + (size_t)s4.w * 16 + jg * 2;
        float4 v0a = __ldg(r0), v0b = __ldg(r0 + 1);
        float4 v1a = __ldg(r1), v1b = __ldg(r1 + 1);
        float4 v2a = __ldg(r2), v2b = __ldg(r2 + 1);
        float4 v3a = __ldg(r3), v3b = __ldg(r3 + 1);
        add4(acc0, v0a); add4(acc1, v0b);
        add4(acc0, v1a); add4(acc1, v1b);
        add4(acc0, v2a); add4(acc1, v2b);
        add4(acc0, v3a); add4(acc1, v3b);
    }
    for (; i < dg; i++) {
        int s0 = __ldg(ep + i);
        const float4* r0 = z4 + (size_t)s0 * 16 + jg * 2;
        add4(acc0, __ldg(r0));
        add4(acc1, __ldg(r0 + 1));
    }

    float di = g_dinv[node];
    acc0.x *= di; acc0.y *= di; acc0.z *= di; acc0.w *= di;
    acc1.x *= di; acc1.y *= di; acc1.z *= di; acc1.w *= di;
    int g = __ldg(batch + node);
    atomicAdd((float4*)(g_pool + g * HID + jg * 8), acc0);
    atomicAdd((float4*)(g_pool + g * HID + jg * 8 + 4), acc1);
    if (jg == 0) atomicAdd(&g_cnt[g], 1.0f);
}

__global__ void k_finalize(float* __restrict__ out,
                           const float* __restrict__ b2) {
    int t = blockIdx.x * blockDim.x + threadIdx.x;
    if (t >= GMAX * HID) return;
    int g = t >> 6, j = t & 63;
    out[t] = g_pool[t] / fmaxf(g_cnt[g], 1.0f) + b2[j];
}

// ================= launch (single stream, serial) =================
extern "C" void kernel_launch(void* const* d_in, const int* in_sizes, int n_in,
                              void* d_out, int out_size) {
    const float* x     = (const float*)d_in[0];
    const int*   eidx  = (const int*)d_in[1];
    const int*   batch = (const int*)d_in[2];
    const float* W1    = (const float*)d_in[3];
    const float* b1    = (const float*)d_in[4];
    const float* W2    = (const float*)d_in[5];
    const float* b2    = (const float*)d_in[6];
    float*       out   = (float*)d_out;

    const int n = in_sizes[0] / 128;
    const int E = in_sizes[1] / 2;
    const int* src = eidx;
    const int* dst = eidx + E;

    float *z, *z2;
    cudaGetSymbolAddress((void**)&z,  g_bufZ);
    cudaGetSymbolAddress((void**)&z2, g_bufZ2);

    const int B = 256;
    const int NBn = (n + 255) / 256;
    const int NBe = (E + 255) / 256;
    const int gemm_grid = (n + 127) / 128;
    const int agg_grid  = (n * 8 + B - 1) / B;

    const int smem1 = (128 * (64 + 4) + 128 * 64) * 4;         // 67584 B
    const int smemF = (128 * (64 + 4) + 64 * 64 + 64) * 4;     // 51456 B
    cudaFuncSetAttribute(k_gemm1,
                         cudaFuncAttributeMaxDynamicSharedMemorySize, smem1);
    cudaFuncSetAttribute(k_agg_gemm2,
                         cudaFuncAttributeMaxDynamicSharedMemorySize, smemF);

    // ELL build (1 edge pass) + dinv + pool zeroing
    k_init<<<NBn, B>>>(n);
    k_ell_fill<<<NBe, B>>>(src, dst, E);
    k_dinv<<<NBn, B>>>(n);

    // layer-1 GEMM: z1 = (x@W1)*dinv
    k_gemm1<<<gemm_grid, 256, smem1>>>(x, W1, z, n);

    // fused aggregate-1 + transform + GEMM2 -> z2
    k_agg_gemm2<<<gemm_grid, 256, smemF>>>(z, W2, b1, z2, n);

    // aggregate-2 fused with mean pool
    k_agg_pool<<<agg_grid, B>>>(z2, batch, n);
    k_finalize<<<(GMAX * HID + B - 1) / B, B>>>(out, b2);
}

// round 12
// speedup vs baseline: 1.2664x; 1.0922x over previous
#include <cuda_runtime.h>
#include <cuda_fp16.h>
#include <cstdint>

#define NMAX 100000
#define EMAX 1600000
#define GMAX 128
#define HID  64
#define CAP  64      // ELL width; in-deg ~ Poisson(16), P(overflow) ~ 1e-13

// ---------------- scratch (no allocations allowed) ----------------
__device__ float  g_dinv[NMAX];
__device__ int    g_deg[NMAX];
__device__ int    g_ell[(size_t)NMAX * CAP];
__device__ __half g_z1h[(size_t)NMAX * HID];   // z1 = (x@W1)*dinv, fp16
__device__ __half g_z2h[(size_t)NMAX * HID];   // z2, fp16
__device__ float  g_pool[GMAX * HID];
__device__ float  g_cnt[GMAX];

// accumulate a 16B half8 granule into 8 fp32 accumulators
__device__ __forceinline__ void acc_half8(float* a, uint4 v) {
    const __half2* h = (const __half2*)&v;
    float2 f0 = __half22float2(h[0]);
    float2 f1 = __half22float2(h[1]);
    float2 f2 = __half22float2(h[2]);
    float2 f3 = __half22float2(h[3]);
    a[0] += f0.x; a[1] += f0.y; a[2] += f1.x; a[3] += f1.y;
    a[4] += f2.x; a[5] += f2.y; a[6] += f3.x; a[7] += f3.y;
}

__device__ __forceinline__ uint4 pack_half8(const float* f) {
    __half2 h[4];
    h[0] = __floats2half2_rn(f[0], f[1]);
    h[1] = __floats2half2_rn(f[2], f[3]);
    h[2] = __floats2half2_rn(f[4], f[5]);
    h[3] = __floats2half2_rn(f[6], f[7]);
    return *(uint4*)h;
}

// ================= graph build (ELL, one edge pass) =================
__global__ void k_init(int n) {
    int i = blockIdx.x * blockDim.x + threadIdx.x;
    if (i < n) g_deg[i] = 0;
    if (i < GMAX * HID) g_pool[i] = 0.f;
    if (i < GMAX) g_cnt[i] = 0.f;
}

__global__ void k_ell_fill(const int* __restrict__ src,
                           const int* __restrict__ dst, int E) {
    int e = blockIdx.x * blockDim.x + threadIdx.x;
    if (e >= E) return;
    int d = dst[e];
    int p = atomicAdd(&g_deg[d], 1);
    g_ell[(size_t)d * CAP + p] = src[e];
}

__global__ void k_dinv(int n) {
    int i = blockIdx.x * blockDim.x + threadIdx.x;
    if (i < n) g_dinv[i] = rsqrtf((float)g_deg[i] + 1.0f);
}

// ================= split-K tiled GEMM (layer 1) =================
// z1[node,:] = (x[node,:] @ W1) * dinv[node]  -> fp16
__global__ void __launch_bounds__(256)
k_gemm1(const float* __restrict__ X,
        const float* __restrict__ Wg,
        __half* __restrict__ Zh, int n) {
    constexpr int K  = 128;
    constexpr int KC = 64;
    constexpr int S  = KC + 4;
    extern __shared__ float smf[];
    float* Xs = smf;                 // [128][68]
    float* Ws = smf + 128 * S;       // [128][64]

    const int tid  = threadIdx.x;
    const int base = blockIdx.x * 128;

    for (int i = tid; i < K * 16; i += 256)
        ((float4*)Ws)[i] = ((const float4*)Wg)[i];

    const int row0 = (tid >> 3) * 4;
    const int col0 = (tid & 7) * 8;

    float acc[4][8];
#pragma unroll
    for (int i = 0; i < 4; i++)
#pragma unroll
        for (int j = 0; j < 8; j++) acc[i][j] = 0.f;

#pragma unroll
    for (int c = 0; c < K / KC; c++) {
        __syncthreads();
        for (int f = tid; f < 128 * (KC / 4); f += 256) {
            int m  = f >> 4;
            int kc = f & 15;
            int node = base + m;
            float4 v = make_float4(0.f, 0.f, 0.f, 0.f);
            if (node < n)
                v = ((const float4*)(X + (size_t)node * K + c * KC))[kc];
            *(float4*)(Xs + m * S + kc * 4) = v;
        }
        __syncthreads();

#pragma unroll 4
        for (int k = 0; k < KC; k++) {
            float a0 = Xs[(row0 + 0) * S + k];
            float a1 = Xs[(row0 + 1) * S + k];
            float a2 = Xs[(row0 + 2) * S + k];
            float a3 = Xs[(row0 + 3) * S + k];
            const float* wrow = Ws + (c * KC + k) * 64 + col0;
            float4 blo = *(const float4*)wrow;
            float4 bhi = *(const float4*)(wrow + 4);
            float b[8] = {blo.x, blo.y, blo.z, blo.w, bhi.x, bhi.y, bhi.z, bhi.w};
#pragma unroll
            for (int j = 0; j < 8; j++) {
                acc[0][j] = fmaf(a0, b[j], acc[0][j]);
                acc[1][j] = fmaf(a1, b[j], acc[1][j]);
                acc[2][j] = fmaf(a2, b[j], acc[2][j]);
                acc[3][j] = fmaf(a3, b[j], acc[3][j]);
            }
        }
    }

#pragma unroll
    for (int i = 0; i < 4; i++) {
        int node = base + row0 + i;
        if (node < n) {
            float di = g_dinv[node];
            float f[8];
#pragma unroll
            for (int j = 0; j < 8; j++) f[j] = acc[i][j] * di;
            *(uint4*)(Zh + (size_t)node * HID + col0) = pack_half8(f);
        }
    }
}

// ========== FUSED: aggregate-1 + input-transform + GEMM2 ==========
// Phase A (8 lanes/node, 16B fp16 each): S = z1[d] + Σ z1[s]  (fp32 acc)
//   x2 = relu(dinv[d]*S + b1) -> GEMM X-tile in smem (fp32).
// Phase B: z2 = (x2 @ W2) * dinv[d] -> fp16
__global__ void __launch_bounds__(256)
k_agg_gemm2(const __half* __restrict__ z1h,
            const float* __restrict__ W2,
            const float* __restrict__ b1,
            __half* __restrict__ Z2h, int n) {
    constexpr int BM = 128;
    constexpr int K  = 64;
    constexpr int S  = K + 4;
    extern __shared__ float smf[];
    float* Xs = smf;                 // [128][68]
    float* Ws = smf + BM * S;        // [64][64]
    float* bs = Ws + K * 64;         // [64]

    const int tid  = threadIdx.x;
    const int base = blockIdx.x * BM;

    for (int i = tid; i < K * 16; i += 256)
        ((float4*)Ws)[i] = ((const float4*)W2)[i];
    if (tid < 64) bs[tid] = b1[tid];

    const uint4* z16 = (const uint4*)z1h;     // 8 granules of 16B per row
#pragma unroll
    for (int p = 0; p < 4; p++) {             // 128 nodes * 8 lanes = 1024
        int t  = tid + p * 256;
        int m  = t >> 3;
        int jg = t & 7;                        // lane owns cols jg*8..jg*8+7
        int node = base + m;
        float a[8] = {0.f,0.f,0.f,0.f,0.f,0.f,0.f,0.f};
        if (node < n) {
            acc_half8(a, __ldg(z16 + (size_t)node * 8 + jg));   // self term

            const int dg = __ldg(g_deg + node);
            const int* ep = g_ell + (size_t)node * CAP;
            int i = 0;
            for (; i + 4 <= dg; i += 4) {
                int4 s4 = __ldg((const int4*)(ep + i));
                uint4 v0 = __ldg(z16 + (size_t)s4.x * 8 + jg);
                uint4 v1 = __ldg(z16 + (size_t)s4.y * 8 + jg);
                uint4 v2 = __ldg(z16 + (size_t)s4.z * 8 + jg);
                uint4 v3 = __ldg(z16 + (size_t)s4.w * 8 + jg);
                acc_half8(a, v0); acc_half8(a, v1);
                acc_half8(a, v2); acc_half8(a, v3);
            }
            for (; i < dg; i++) {
                int s0 = __ldg(ep + i);
                acc_half8(a, __ldg(z16 + (size_t)s0 * 8 + jg));
            }

            float dn = __ldg(g_dinv + node);
            int k0 = jg * 8;
#pragma unroll
            for (int j = 0; j < 8; j++)
                a[j] = fmaxf(fmaf(a[j], dn, bs[k0 + j]), 0.f);
        }
        *(float4*)(Xs + m * S + jg * 8)     = make_float4(a[0], a[1], a[2], a[3]);
        *(float4*)(Xs + m * S + jg * 8 + 4) = make_float4(a[4], a[5], a[6], a[7]);
    }
    __syncthreads();

    // ---- phase B: tile GEMM, epilogue * dinv -> fp16 ----
    const int row0 = (tid >> 3) * 4;
    const int col0 = (tid & 7) * 8;

    float acc[4][8];
#pragma unroll
    for (int i = 0; i < 4; i++)
#pragma unroll
        for (int j = 0; j < 8; j++) acc[i][j] = 0.f;

#pragma unroll 4
    for (int k = 0; k < K; k++) {
        float a0 = Xs[(row0 + 0) * S + k];
        float a1 = Xs[(row0 + 1) * S + k];
        float a2 = Xs[(row0 + 2) * S + k];
        float a3 = Xs[(row0 + 3) * S + k];
        float4 blo = *(float4*)(Ws + k * 64 + col0);
        float4 bhi = *(float4*)(Ws + k * 64 + col0 + 4);
        float b[8] = {blo.x, blo.y, blo.z, blo.w, bhi.x, bhi.y, bhi.z, bhi.w};
#pragma unroll
        for (int j = 0; j < 8; j++) {
            acc[0][j] = fmaf(a0, b[j], acc[0][j]);
            acc[1][j] = fmaf(a1, b[j], acc[1][j]);
            acc[2][j] = fmaf(a2, b[j], acc[2][j]);
            acc[3][j] = fmaf(a3, b[j], acc[3][j]);
        }
    }

#pragma unroll
    for (int i = 0; i < 4; i++) {
        int node = base + row0 + i;
        if (node < n) {
            float di = g_dinv[node];
            float f[8];
#pragma unroll
            for (int j = 0; j < 8; j++) f[j] = acc[i][j] * di;
            *(uint4*)(Z2h + (size_t)node * HID + col0) = pack_half8(f);
        }
    }
}

// ============ aggregate-2 (8 lanes/node, fp16) fused with mean pool =======
__global__ void k_agg_pool(const __half* __restrict__ zh,
                           const int* __restrict__ batch, int n) {
    int t    = blockIdx.x * blockDim.x + threadIdx.x;
    int node = t >> 3;
    int jg   = t & 7;
    if (node >= n) return;

    const uint4* z16 = (const uint4*)zh;
    float a[8] = {0.f,0.f,0.f,0.f,0.f,0.f,0.f,0.f};
    acc_half8(a, __ldg(z16 + (size_t)node * 8 + jg));      // self term

    const int dg = __ldg(g_deg + node);
    const int* ep = g_ell + (size_t)node * CAP;

    int i = 0;
    for (; i + 4 <= dg; i += 4) {
        int4 s4 = __ldg((const int4*)(ep + i));
        uint4 v0 = __ldg(z16 + (size_t)s4.x * 8 + jg);
        uint4 v1 = __ldg(z16 + (size_t)s4.y * 8 + jg);
        uint4 v2 = __ldg(z16 + (size_t)s4.z * 8 + jg);
        uint4 v3 = __ldg(z16 + (size_t)s4.w * 8 + jg);
        acc_half8(a, v0); acc_half8(a, v1);
        acc_half8(a, v2); acc_half8(a, v3);
    }
    for (; i < dg; i++) {
        int s0 = __ldg(ep + i);
        acc_half8(a, __ldg(z16 + (size_t)s0 * 8 + jg));
    }

    float di = g_dinv[node];
    float4 lo = make_float4(a[0]*di, a[1]*di, a[2]*di, a[3]*di);
    float4 hi = make_float4(a[4]*di, a[5]*di, a[6]*di, a[7]*di);
    int g = __ldg(batch + node);
    atomicAdd((float4*)(g_pool + g * HID + jg * 8), lo);
    atomicAdd((float4*)(g_pool + g * HID + jg * 8 + 4), hi);
    if (jg == 0) atomicAdd(&g_cnt[g], 1.0f);
}

__global__ void k_finalize(float* __restrict__ out,
                           const float* __restrict__ b2) {
    int t = blockIdx.x * blockDim.x + threadIdx.x;
    if (t >= GMAX * HID) return;
    int g = t >> 6, j = t & 63;
    out[t] = g_pool[t] / fmaxf(g_cnt[g], 1.0f) + b2[j];
}

// ================= launch (single stream, serial) =================
extern "C" void kernel_launch(void* const* d_in, const int* in_sizes, int n_in,
                              void* d_out, int out_size) {
    const float* x     = (const float*)d_in[0];
    const int*   eidx  = (const int*)d_in[1];
    const int*   batch = (const int*)d_in[2];
    const float* W1    = (const float*)d_in[3];
    const float* b1    = (const float*)d_in[4];
    const float* W2    = (const float*)d_in[5];
    const float* b2    = (const float*)d_in[6];
    float*       out   = (float*)d_out;

    const int n = in_sizes[0] / 128;
    const int E = in_sizes[1] / 2;
    const int* src = eidx;
    const int* dst = eidx + E;

    __half *z1h, *z2h;
    cudaGetSymbolAddress((void**)&z1h, g_z1h);
    cudaGetSymbolAddress((void**)&z2h, g_z2h);

    const int B = 256;
    const int NBn = (n + 255) / 256;
    const int NBe = (E + 255) / 256;
    const int gemm_grid = (n + 127) / 128;
    const int agg_grid  = (n * 8 + B - 1) / B;

    const int smem1 = (128 * (64 + 4) + 128 * 64) * 4;         // 67584 B
    const int smemF = (128 * (64 + 4) + 64 * 64 + 64) * 4;     // 51456 B
    cudaFuncSetAttribute(k_gemm1,
                         cudaFuncAttributeMaxDynamicSharedMemorySize, smem1);
    cudaFuncSetAttribute(k_agg_gemm2,
                         cudaFuncAttributeMaxDynamicSharedMemorySize, smemF);

    // ELL build (1 edge pass) + dinv + pool zeroing
    k_init<<<NBn, B>>>(n);
    k_ell_fill<<<NBe, B>>>(src, dst, E);
    k_dinv<<<NBn, B>>>(n);

    // layer-1 GEMM: z1 = (x@W1)*dinv -> fp16
    k_gemm1<<<gemm_grid, 256, smem1>>>(x, W1, z1h, n);

    // fused aggregate-1 + transform + GEMM2 -> z2 (fp16)
    k_agg_gemm2<<<gemm_grid, 256, smemF>>>(z1h, W2, b1, z2h, n);

    // aggregate-2 fused with mean pool
    k_agg_pool<<<agg_grid, B>>>(z2h, batch, n);
    k_finalize<<<(GMAX * HID + B - 1) / B, B>>>(out, b2);
}

// round 13
// speedup vs baseline: 1.4879x; 1.1749x over previous
#include <cuda_runtime.h>
#include <cuda_fp16.h>
#include <cstdint>

#define NMAX 100000
#define EMAX 1600000
#define GMAX 128
#define HID  64
#define CAP  64      // ELL width; in-deg ~ Poisson(16), P(overflow) ~ 1e-13

// ---------------- scratch (no allocations allowed) ----------------
__device__ float  g_dinv[NMAX];
__device__ int    g_deg[NMAX];
__device__ int    g_ell[(size_t)NMAX * CAP];
__device__ __half g_z1h[(size_t)NMAX * HID];   // z1 = (x@W1)*dinv, fp16
__device__ __half g_z2h[(size_t)NMAX * HID];   // z2, fp16
__device__ float  g_pool[GMAX * HID];
__device__ float  g_cnt[GMAX];

// ---------------- helpers ----------------
__device__ __forceinline__ void acc_half8(float* a, uint4 v) {
    const __half2* h = (const __half2*)&v;
    float2 f0 = __half22float2(h[0]);
    float2 f1 = __half22float2(h[1]);
    float2 f2 = __half22float2(h[2]);
    float2 f3 = __half22float2(h[3]);
    a[0] += f0.x; a[1] += f0.y; a[2] += f1.x; a[3] += f1.y;
    a[4] += f2.x; a[5] += f2.y; a[6] += f3.x; a[7] += f3.y;
}
__device__ __forceinline__ uint4 pack_half8(const float* f) {
    __half2 h[4];
    h[0] = __floats2half2_rn(f[0], f[1]);
    h[1] = __floats2half2_rn(f[2], f[3]);
    h[2] = __floats2half2_rn(f[4], f[5]);
    h[3] = __floats2half2_rn(f[6], f[7]);
    return *(uint4*)h;
}

__device__ __forceinline__ void ldsm_x4(uint32_t* r, uint32_t addr) {
    asm volatile("ldmatrix.sync.aligned.m8n8.x4.shared.b16 {%0,%1,%2,%3}, [%4];"
                 : "=r"(r[0]), "=r"(r[1]), "=r"(r[2]), "=r"(r[3]) : "r"(addr));
}
__device__ __forceinline__ void ldsm_x4_t(uint32_t* r, uint32_t addr) {
    asm volatile("ldmatrix.sync.aligned.m8n8.x4.trans.shared.b16 {%0,%1,%2,%3}, [%4];"
                 : "=r"(r[0]), "=r"(r[1]), "=r"(r[2]), "=r"(r[3]) : "r"(addr));
}
__device__ __forceinline__ void mma16816(float* c, const uint32_t* a,
                                         uint32_t b0, uint32_t b1) {
    asm volatile(
        "mma.sync.aligned.m16n8k16.row.col.f32.f16.f16.f32 "
        "{%0,%1,%2,%3},{%4,%5,%6,%7},{%8,%9},{%0,%1,%2,%3};"
        : "+f"(c[0]), "+f"(c[1]), "+f"(c[2]), "+f"(c[3])
        : "r"(a[0]), "r"(a[1]), "r"(a[2]), "r"(a[3]), "r"(b0), "r"(b1));
}
__device__ __forceinline__ uint2 split_pack4(float4 v) {
    __half h0 = __float2half(v.x), h1 = __float2half(v.y);
    __half h2 = __float2half(v.z), h3 = __float2half(v.w);
    uint2 r;
    r.x = (uint32_t)__half_as_ushort(h0) | ((uint32_t)__half_as_ushort(h1) << 16);
    r.y = (uint32_t)__half_as_ushort(h2) | ((uint32_t)__half_as_ushort(h3) << 16);
    return r;
}
__device__ __forceinline__ uint2 split_pack4_lo(float4 v) {
    __half h0 = __float2half(v.x); __half l0 = __float2half(v.x - __half2float(h0));
    __half h1 = __float2half(v.y); __half l1 = __float2half(v.y - __half2float(h1));
    __half h2 = __float2half(v.z); __half l2 = __float2half(v.z - __half2float(h2));
    __half h3 = __float2half(v.w); __half l3 = __float2half(v.w - __half2float(h3));
    uint2 r;
    r.x = (uint32_t)__half_as_ushort(l0) | ((uint32_t)__half_as_ushort(l1) << 16);
    r.y = (uint32_t)__half_as_ushort(l2) | ((uint32_t)__half_as_ushort(l3) << 16);
    return r;
}

// ================= graph build (ELL, one edge pass) =================
__global__ void k_init(int n) {
    int i = blockIdx.x * blockDim.x + threadIdx.x;
    if (i < n) g_deg[i] = 0;
    if (i < GMAX * HID) g_pool[i] = 0.f;
    if (i < GMAX) g_cnt[i] = 0.f;
}
__global__ void k_ell_fill(const int* __restrict__ src,
                           const int* __restrict__ dst, int E) {
    int e = blockIdx.x * blockDim.x + threadIdx.x;
    if (e >= E) return;
    int d = dst[e];
    int p = atomicAdd(&g_deg[d], 1);
    g_ell[(size_t)d * CAP + p] = src[e];
}
__global__ void k_dinv(int n) {
    int i = blockIdx.x * blockDim.x + threadIdx.x;
    if (i < n) g_dinv[i] = rsqrtf((float)g_deg[i] + 1.0f);
}

// ================= tensor-core GEMM1 (split-fp16 HMMA) =================
// z1[node,:] = (x[node,:] @ W1) * dinv[node] -> fp16
// x = xh+xl, W = Wh+Wl (fp16); Y = xh@Wh + xh@Wl + xl@Wh (f32 acc).
// smem: padded 72-half rows (144B stride -> ldmatrix conflict-free).
#define SW 72
#define OFF_WH 0
#define OFF_WL 18432
#define OFF_AH 36864
#define OFF_AL 55296
#define SM_G1  73728

__global__ void __launch_bounds__(256)
k_gemm1_mma(const float* __restrict__ X,
            const float* __restrict__ Wg,     // [128][64] fp32
            __half* __restrict__ Zh, int n) {
    extern __shared__ char sm[];
    const uint32_t sbase = (uint32_t)__cvta_generic_to_shared(sm);
    const int tid  = threadIdx.x;
    const int wid  = tid >> 5;
    const int lane = tid & 31;
    const int base = blockIdx.x * 128;

    // ---- stage W (all K=128 rows): fp32 -> (Wh, Wl) ----
    for (int i = tid; i < 128 * 16; i += 256) {
        int row = i >> 4, c4 = i & 15;
        float4 w = ((const float4*)Wg)[i];
        uint2 hi = split_pack4(w);
        uint2 lo = split_pack4_lo(w);
        *(uint2*)(sm + OFF_WH + (row * SW + c4 * 4) * 2) = hi;
        *(uint2*)(sm + OFF_WL + (row * SW + c4 * 4) * 2) = lo;
    }

    const int m0 = wid * 16;               // warp's row block
    float c[8][4];
#pragma unroll
    for (int j = 0; j < 8; j++)
#pragma unroll
        for (int q = 0; q < 4; q++) c[j][q] = 0.f;

    // ldmatrix lane addressing (constant per lane)
    const int a_row = m0 + (lane & 15);
    const int a_koff = (lane >> 4) << 3;              // 0 or 8
    const int b_rowoff = ((lane & 8) ? 8 : 0) + (lane & 7);
    const int b_noff = (lane >> 4) << 3;              // 0 or 8

#pragma unroll
    for (int ch = 0; ch < 2; ch++) {
        // ---- stage A chunk (k global ch*64 .. +63) ----
        __syncthreads();
        for (int i = tid; i < 128 * 16; i += 256) {
            int m = i >> 4, c4 = i & 15;
            int node = base + m;
            float4 v = make_float4(0.f, 0.f, 0.f, 0.f);
            if (node < n)
                v = ((const float4*)(X + (size_t)node * 128 + ch * 64))[c4];
            uint2 hi = split_pack4(v);
            uint2 lo = split_pack4_lo(v);
            *(uint2*)(sm + OFF_AH + (m * SW + c4 * 4) * 2) = hi;
            *(uint2*)(sm + OFF_AL + (m * SW + c4 * 4) * 2) = lo;
        }
        __syncthreads();

#pragma unroll
        for (int ks = 0; ks < 4; ks++) {
            const int k0l = ks * 16;                  // chunk-local k
            const int k0g = ch * 64 + k0l;            // global k (W rows)

            uint32_t ah[4], al[4];
            uint32_t a_addr = sbase + OFF_AH + (a_row * SW + k0l + a_koff) * 2;
            ldsm_x4(ah, a_addr);
            ldsm_x4(al, a_addr + (OFF_AL - OFF_AH));

            const int b_row = k0g + b_rowoff;
#pragma unroll
            for (int np = 0; np < 4; np++) {          // n-pairs: cols np*16
                uint32_t bh[4], bl[4];
                uint32_t b_addr = sbase + OFF_WH + (b_row * SW + np * 16 + b_noff) * 2;
                ldsm_x4_t(bh, b_addr);
                ldsm_x4_t(bl, b_addr + (OFF_WL - OFF_WH));
                // n-tile 2*np   : frags {bh[0],bh[1]} / {bl[0],bl[1]}
                // n-tile 2*np+1 : frags {bh[2],bh[3]} / {bl[2],bl[3]}
                mma16816(c[2 * np],     ah, bh[0], bh[1]);
                mma16816(c[2 * np],     ah, bl[0], bl[1]);
                mma16816(c[2 * np],     al, bh[0], bh[1]);
                mma16816(c[2 * np + 1], ah, bh[2], bh[3]);
                mma16816(c[2 * np + 1], ah, bl[2], bl[3]);
                mma16816(c[2 * np + 1], al, bh[2], bh[3]);
            }
        }
    }

    // ---- epilogue: scale by dinv, pack fp16, store ----
    const int r0 = m0 + (lane >> 2);        // rows r0 and r0+8
    const int cc = (lane & 3) * 2;
    int node0 = base + r0;
    int node1 = node0 + 8;
    float d0 = (node0 < n) ? g_dinv[node0] : 0.f;
    float d1 = (node1 < n) ? g_dinv[node1] : 0.f;
#pragma unroll
    for (int j = 0; j < 8; j++) {
        int col = j * 8 + cc;
        if (node0 < n) {
            __half2 h = __floats2half2_rn(c[j][0] * d0, c[j][1] * d0);
            *(__half2*)(Zh + (size_t)node0 * HID + col) = h;
        }
        if (node1 < n) {
            __half2 h = __floats2half2_rn(c[j][2] * d1, c[j][3] * d1);
            *(__half2*)(Zh + (size_t)node1 * HID + col) = h;
        }
    }
}

// ========== FUSED: aggregate-1 + input-transform + GEMM2 ==========
__global__ void __launch_bounds__(256)
k_agg_gemm2(const __half* __restrict__ z1h,
            const float* __restrict__ W2,
            const float* __restrict__ b1,
            __half* __restrict__ Z2h, int n) {
    constexpr int BM = 128;
    constexpr int K  = 64;
    constexpr int S  = K + 4;
    extern __shared__ float smf[];
    float* Xs = smf;                 // [128][68]
    float* Ws = smf + BM * S;        // [64][64]
    float* bs = Ws + K * 64;         // [64]

    const int tid  = threadIdx.x;
    const int base = blockIdx.x * BM;

    for (int i = tid; i < K * 16; i += 256)
        ((float4*)Ws)[i] = ((const float4*)W2)[i];
    if (tid < 64) bs[tid] = b1[tid];

    const uint4* z16 = (const uint4*)z1h;
#pragma unroll
    for (int p = 0; p < 4; p++) {
        int t  = tid + p * 256;
        int m  = t >> 3;
        int jg = t & 7;
        int node = base + m;
        float a[8] = {0.f,0.f,0.f,0.f,0.f,0.f,0.f,0.f};
        if (node < n) {
            acc_half8(a, __ldg(z16 + (size_t)node * 8 + jg));

            const int dg = __ldg(g_deg + node);
            const int* ep = g_ell + (size_t)node * CAP;
            int i = 0;
            for (; i + 4 <= dg; i += 4) {
                int4 s4 = __ldg((const int4*)(ep + i));
                uint4 v0 = __ldg(z16 + (size_t)s4.x * 8 + jg);
                uint4 v1 = __ldg(z16 + (size_t)s4.y * 8 + jg);
                uint4 v2 = __ldg(z16 + (size_t)s4.z * 8 + jg);
                uint4 v3 = __ldg(z16 + (size_t)s4.w * 8 + jg);
                acc_half8(a, v0); acc_half8(a, v1);
                acc_half8(a, v2); acc_half8(a, v3);
            }
            for (; i < dg; i++) {
                int s0 = __ldg(ep + i);
                acc_half8(a, __ldg(z16 + (size_t)s0 * 8 + jg));
            }

            float dn = __ldg(g_dinv + node);
            int k0 = jg * 8;
#pragma unroll
            for (int j = 0; j < 8; j++)
                a[j] = fmaxf(fmaf(a[j], dn, bs[k0 + j]), 0.f);
        }
        *(float4*)(Xs + m * S + jg * 8)     = make_float4(a[0], a[1], a[2], a[3]);
        *(float4*)(Xs + m * S + jg * 8 + 4) = make_float4(a[4], a[5], a[6], a[7]);
    }
    __syncthreads();

    const int row0 = (tid >> 3) * 4;
    const int col0 = (tid & 7) * 8;

    float acc[4][8];
#pragma unroll
    for (int i = 0; i < 4; i++)
#pragma unroll
        for (int j = 0; j < 8; j++) acc[i][j] = 0.f;

#pragma unroll 4
    for (int k = 0; k < K; k++) {
        float a0 = Xs[(row0 + 0) * S + k];
        float a1 = Xs[(row0 + 1) * S + k];
        float a2 = Xs[(row0 + 2) * S + k];
        float a3 = Xs[(row0 + 3) * S + k];
        float4 blo = *(float4*)(Ws + k * 64 + col0);
        float4 bhi = *(float4*)(Ws + k * 64 + col0 + 4);
        float b[8] = {blo.x, blo.y, blo.z, blo.w, bhi.x, bhi.y, bhi.z, bhi.w};
#pragma unroll
        for (int j = 0; j < 8; j++) {
            acc[0][j] = fmaf(a0, b[j], acc[0][j]);
            acc[1][j] = fmaf(a1, b[j], acc[1][j]);
            acc[2][j] = fmaf(a2, b[j], acc[2][j]);
            acc[3][j] = fmaf(a3, b[j], acc[3][j]);
        }
    }

#pragma unroll
    for (int i = 0; i < 4; i++) {
        int node = base + row0 + i;
        if (node < n) {
            float di = g_dinv[node];
            float f[8];
#pragma unroll
            for (int j = 0; j < 8; j++) f[j] = acc[i][j] * di;
            *(uint4*)(Z2h + (size_t)node * HID + col0) = pack_half8(f);
        }
    }
}

// ============ aggregate-2 (8 lanes/node, fp16) fused with mean pool =======
__global__ void k_agg_pool(const __half* __restrict__ zh,
                           const int* __restrict__ batch, int n) {
    int t    = blockIdx.x * blockDim.x + threadIdx.x;
    int node = t >> 3;
    int jg   = t & 7;
    if (node >= n) return;

    const uint4* z16 = (const uint4*)zh;
    float a[8] = {0.f,0.f,0.f,0.f,0.f,0.f,0.f,0.f};
    acc_half8(a, __ldg(z16 + (size_t)node * 8 + jg));

    const int dg = __ldg(g_deg + node);
    const int* ep = g_ell + (size_t)node * CAP;

    int i = 0;
    for (; i + 4 <= dg; i += 4) {
        int4 s4 = __ldg((const int4*)(ep + i));
        uint4 v0 = __ldg(z16 + (size_t)s4.x * 8 + jg);
        uint4 v1 = __ldg(z16 + (size_t)s4.y * 8 + jg);
        uint4 v2 = __ldg(z16 + (size_t)s4.z * 8 + jg);
        uint4 v3 = __ldg(z16 + (size_t)s4.w * 8 + jg);
        acc_half8(a, v0); acc_half8(a, v1);
        acc_half8(a, v2); acc_half8(a, v3);
    }
    for (; i < dg; i++) {
        int s0 = __ldg(ep + i);
        acc_half8(a, __ldg(z16 + (size_t)s0 * 8 + jg));
    }

    float di = g_dinv[node];
    float4 lo = make_float4(a[0]*di, a[1]*di, a[2]*di, a[3]*di);
    float4 hi = make_float4(a[4]*di, a[5]*di, a[6]*di, a[7]*di);
    int g = __ldg(batch + node);
    atomicAdd((float4*)(g_pool + g * HID + jg * 8), lo);
    atomicAdd((float4*)(g_pool + g * HID + jg * 8 + 4), hi);
    if (jg == 0) atomicAdd(&g_cnt[g], 1.0f);
}

__global__ void k_finalize(float* __restrict__ out,
                           const float* __restrict__ b2) {
    int t = blockIdx.x * blockDim.x + threadIdx.x;
    if (t >= GMAX * HID) return;
    int g = t >> 6, j = t & 63;
    out[t] = g_pool[t] / fmaxf(g_cnt[g], 1.0f) + b2[j];
}

// ================= launch (single stream, serial) =================
extern "C" void kernel_launch(void* const* d_in, const int* in_sizes, int n_in,
                              void* d_out, int out_size) {
    const float* x     = (const float*)d_in[0];
    const int*   eidx  = (const int*)d_in[1];
    const int*   batch = (const int*)d_in[2];
    const float* W1    = (const float*)d_in[3];
    const float* b1    = (const float*)d_in[4];
    const float* W2    = (const float*)d_in[5];
    const float* b2    = (const float*)d_in[6];
    float*       out   = (float*)d_out;

    const int n = in_sizes[0] / 128;
    const int E = in_sizes[1] / 2;
    const int* src = eidx;
    const int* dst = eidx + E;

    __half *z1h, *z2h;
    cudaGetSymbolAddress((void**)&z1h, g_z1h);
    cudaGetSymbolAddress((void**)&z2h, g_z2h);

    const int B = 256;
    const int NBn = (n + 255) / 256;
    const int NBe = (E + 255) / 256;
    const int gemm_grid = (n + 127) / 128;
    const int agg_grid  = (n * 8 + B - 1) / B;

    const int smemF = (128 * (64 + 4) + 64 * 64 + 64) * 4;     // 51456 B
    cudaFuncSetAttribute(k_gemm1_mma,
                         cudaFuncAttributeMaxDynamicSharedMemorySize, SM_G1);
    cudaFuncSetAttribute(k_agg_gemm2,
                         cudaFuncAttributeMaxDynamicSharedMemorySize, smemF);

    // ELL build (1 edge pass) + dinv + pool zeroing
    k_init<<<NBn, B>>>(n);
    k_ell_fill<<<NBe, B>>>(src, dst, E);
    k_dinv<<<NBn, B>>>(n);

    // layer-1 GEMM on tensor cores: z1 = (x@W1)*dinv -> fp16
    k_gemm1_mma<<<gemm_grid, 256, SM_G1>>>(x, W1, z1h, n);

    // fused aggregate-1 + transform + GEMM2 -> z2 (fp16)
    k_agg_gemm2<<<gemm_grid, 256, smemF>>>(z1h, W2, b1, z2h, n);

    // aggregate-2 fused with mean pool
    k_agg_pool<<<agg_grid, B>>>(z2h, batch, n);
    k_finalize<<<(GMAX * HID + B - 1) / B, B>>>(out, b2);
}